// round 16
// baseline (speedup 1.0000x reference)
#include <cuda_runtime.h>
#include <cuda_bf16.h>

// video [B=8, C=3, T=32, H=224, W=224] fp32.
// out[b,c,t,y,x] = clip01( clamped-bilinear sample of frame (b,c,t) at
//   src = (coord + shake + 0.5) * (224/240) - 0.5 )
// (trilinear resize 224->240 has identity T axis; jax boundary weight
//  renormalization for the linear kernel == coordinate clamping.)
//
// R15: R14 + streaming read policy. Input is read exactly once (154 MB >>
// L2), so __ldcs (evict-first) on the video gather stops the read stream
// thrashing L2 against the __stcs write stream. Structure unchanged:
// zero-smem shuffle gather, 16 batched loads, split consumption so stores
// overlap in-flight loads, branch-free select epilogue.

#define HH 224
#define WW 224
#define TT 32
#define NPLANES 768                     // B*C*T
#define TILE_Y 16
#define TILES_PER_PLANE (HH / TILE_Y)   // 14
#define THREADS 224
#define SCALE_F (14.0f / 15.0f)
#define FULLMASK 0xFFFFFFFFu

__device__ __forceinline__ float vlerp(const float* h, int y, float sy, int base)
{
    float fl  = floorf(sy);
    float fy  = sy - fl;
    int   idx = (int)fl - base;          // provably y or y-1
    bool  rep = (idx != y);
    float a   = rep ? h[y - 1] : h[y];
    float b   = rep ? h[y]     : h[y + 1];
    return __saturatef(fmaf(fy, b - a, a));
}

__global__ __launch_bounds__(THREADS) void shake_bilinear_ldcs_kernel(
    const float* __restrict__ vid,
    const int*   __restrict__ sh,
    const int*   __restrict__ sw,
    float*       __restrict__ out)
{
    int blk  = blockIdx.x;
    int tile = blk % TILES_PER_PLANE;
    int p    = blk / TILES_PER_PLANE;    // plane = (b*C + c)*T + t
    int t    = p & (TT - 1);
    int sht  = __ldg(sh + t);
    int swt  = __ldg(sw + t);
    int yb   = tile * TILE_Y;
    int tid  = threadIdx.x;

    const float* plane = vid + (long long)p * (HH * WW);

    // ---- Horizontal taps via warp-window shuffle ----
    int   x    = tid;                    // 0..223
    int   lane = tid & 31;
    int   wx0  = tid & ~31;              // first x of this warp's strip

    float sx  = ((float)(x + swt) + 0.5f) * SCALE_F - 0.5f;
    float f0  = floorf(sx);
    float fx  = sx - f0;
    int   x0  = (int)f0;
    int   x0c = max(x0, 0);
    int   x1c = min(x0 + 1, WW - 1);

    float sxw   = ((float)(wx0 + swt) + 0.5f) * SCALE_F - 0.5f;
    int   baseX = (int)floorf(sxw);
    int   i0    = x0c - baseX;           // in [0,31]
    int   i1    = x1c - baseX;           // in [0,31]
    int   colL  = min(max(baseX + lane, 0), WW - 1);

    // Base source row for this tile (block-uniform).
    float syb  = ((float)(yb + sht) + 0.5f) * SCALE_F - 0.5f;  // sy at y=0
    int   base = (int)floorf(syb);

    // ---- Issue all 16 gather loads (streaming, evict-first) ----
    float v[16];
    if (base >= 0 && base + 15 < HH) {
        const float* rp = plane + base * WW + colL;
#pragma unroll
        for (int r = 0; r < 16; r++)
            v[r] = __ldcs(rp + r * WW);
    } else {
#pragma unroll
        for (int r = 0; r < 16; r++) {
            int srcr = min(max(base + r, 0), HH - 1);
            v[r] = __ldcs(plane + srcr * WW + colL);
        }
    }

    float* orow = out + (long long)p * (HH * WW) + yb * WW + x;
    float h[16];

    // ---- First half: h[0..7] then outputs y=0..6 (need only h[0..7]) ----
#pragma unroll
    for (int r = 0; r < 8; r++) {
        float a = __shfl_sync(FULLMASK, v[r], i0);
        float b = __shfl_sync(FULLMASK, v[r], i1);
        h[r] = fmaf(fx, b - a, a);
    }
    // y = 0: interval index is always 0.
    {
        float fy = syb - floorf(syb);
        __stcs(orow, __saturatef(fmaf(fy, h[1] - h[0], h[0])));
    }
#pragma unroll
    for (int y = 1; y <= 6; y++) {
        float sy = fmaf((float)y, SCALE_F, syb);
        __stcs(orow + y * WW, vlerp(h, y, sy, base));
    }

    // ---- Second half: h[8..15] then outputs y=7..15 ----
#pragma unroll
    for (int r = 8; r < 16; r++) {
        float a = __shfl_sync(FULLMASK, v[r], i0);
        float b = __shfl_sync(FULLMASK, v[r], i1);
        h[r] = fmaf(fx, b - a, a);
    }
#pragma unroll
    for (int y = 7; y <= 14; y++) {
        float sy = fmaf((float)y, SCALE_F, syb);
        __stcs(orow + y * WW, vlerp(h, y, sy, base));
    }
    // y = 15: interval index is always 14 (margin >= 1/30 >> fp32 noise).
    {
        float sy = fmaf(15.0f, SCALE_F, syb);
        float fy = sy - floorf(sy);
        __stcs(orow + 15 * WW, __saturatef(fmaf(fy, h[15] - h[14], h[14])));
    }
}

extern "C" void kernel_launch(void* const* d_in, const int* in_sizes, int n_in,
                              void* d_out, int out_size)
{
    const float* vid = (const float*)d_in[0];
    const int*   sh  = (const int*)d_in[1];
    const int*   sw  = (const int*)d_in[2];
    float*       out = (float*)d_out;

    int blocks = NPLANES * TILES_PER_PLANE; // 10752
    shake_bilinear_ldcs_kernel<<<blocks, THREADS>>>(vid, sh, sw, out);
}